// round 16
// baseline (speedup 1.0000x reference)
#include <cuda_runtime.h>
#include <cuda_fp16.h>
#include <mma.h>
#include <math.h>
#include <stdint.h>

using namespace nvcuda;

#define Lq 1024
#define Ee 256
#define Hh 8
#define Dd 32
#define LOG2E 1.4426950408889634f
#define QSCALE (0.0625f * LOG2E)

// scratch (allocation-free rule: __device__ globals)
__device__ __half g_q[Lq * Ee];     // projected q (pre-scaled by LOG2E/16)
__device__ __half g_k[Lq * Ee];
__device__ __half g_v[Lq * Ee];
__device__ __half g_ho[Lq * Ee];    // attention output (fp16)
__device__ __half g_hwo[Ee * Ee];   // fp16 Wo (converted inside flash)
__device__ __half g_rel[Lq * Lq];   // lg2(|p_q - p_k| + 1), head-independent

typedef wmma::fragment<wmma::matrix_a, 16, 16, 16, __half, wmma::row_major> FragA;
typedef wmma::fragment<wmma::matrix_b, 16, 16, 16, __half, wmma::col_major> FragBc;
typedef wmma::fragment<wmma::accumulator, 16, 16, 16, float> FragC;

extern __shared__ char dyn_smem[];

__device__ __forceinline__ float ex2f(float x) {
    float y; asm("ex2.approx.f32 %0, %1;" : "=f"(y) : "f"(x)); return y;
}
__device__ __forceinline__ float lg2f(float x) {
    float y; asm("lg2.approx.f32 %0, %1;" : "=f"(y) : "f"(x)); return y;
}
__device__ __forceinline__ void cp16(void* smem, const void* gmem) {
    uint32_t s = (uint32_t)__cvta_generic_to_shared(smem);
    asm volatile("cp.async.cg.shared.global [%0], [%1], 16;\n" :: "r"(s), "l"(gmem));
}
#define CP_COMMIT() asm volatile("cp.async.commit_group;\n" ::: "memory")
#define CP_WAIT1()  asm volatile("cp.async.wait_group 1;\n" ::: "memory")
#define CP_WAIT0()  asm volatile("cp.async.wait_group 0;\n" ::: "memory")

__device__ __forceinline__ uint32_t h2pack(float x, float y) {
    __half2 h = __floats2half2_rn(x, y);
    return *(uint32_t*)&h;
}
__device__ __forceinline__ void ldx4(uint32_t r[4], const void* p) {
    uint32_t a = (uint32_t)__cvta_generic_to_shared(p);
    asm volatile("ldmatrix.sync.aligned.m8n8.x4.shared.b16 {%0,%1,%2,%3}, [%4];"
                 : "=r"(r[0]), "=r"(r[1]), "=r"(r[2]), "=r"(r[3]) : "r"(a));
}
__device__ __forceinline__ void ldx4t(uint32_t r[4], const void* p) {
    uint32_t a = (uint32_t)__cvta_generic_to_shared(p);
    asm volatile("ldmatrix.sync.aligned.m8n8.x4.trans.shared.b16 {%0,%1,%2,%3}, [%4];"
                 : "=r"(r[0]), "=r"(r[1]), "=r"(r[2]), "=r"(r[3]) : "r"(a));
}
__device__ __forceinline__ void mma16816(float c[4], const uint32_t a[4],
                                         uint32_t b0, uint32_t b1) {
    asm volatile("mma.sync.aligned.m16n8k16.row.col.f32.f16.f16.f32 "
                 "{%0,%1,%2,%3}, {%4,%5,%6,%7}, {%8,%9}, {%0,%1,%2,%3};"
                 : "+f"(c[0]), "+f"(c[1]), "+f"(c[2]), "+f"(c[3])
                 : "r"(a[0]), "r"(a[1]), "r"(a[2]), "r"(a[3]), "r"(b0), "r"(b1));
}

// ---------------------------------------------------------------------------
// QKV projection (R14 config), SINGLE-SHOT K=256, inline fp32->fp16.
// Tile 32(M) x 64(N): grid (4, 32, 3) = 384 CTAs, 256 threads, dyn smem 49.5KB.
// Warp map (wr, wc, kh) = 2x2x2 splitK; 2 accumulators per warp.
// Wq scaled by LOG2E/16 (folds 1/sqrt(E) + exp2 base change).
// SIDE JOB: CTAs with z<2 (256 of them) each write 4 rows of g_rel
// (lg2(|pq-pk|+1) fp16) — overlapped with staging; head-independent table.
// ---------------------------------------------------------------------------
__global__ __launch_bounds__(256)
void gemm_qkv_kernel(const float* __restrict__ Q, const float* __restrict__ K_,
                     const float* __restrict__ V,
                     const float* __restrict__ Wq, const float* __restrict__ Wk,
                     const float* __restrict__ Wv,
                     const float* __restrict__ position) {
    const float* A = blockIdx.z == 0 ? Q  : (blockIdx.z == 1 ? K_ : V);
    const float* B = blockIdx.z == 0 ? Wq : (blockIdx.z == 1 ? Wk : Wv);
    __half*      C = blockIdx.z == 0 ? g_q : (blockIdx.z == 1 ? g_k : g_v);
    const float scale = blockIdx.z == 0 ? QSCALE : 1.0f;

    __half (*As)[264] = reinterpret_cast<__half(*)[264]>(dyn_smem);
    __half (*Bs)[264] = reinterpret_cast<__half(*)[264]>(dyn_smem + 16896);

    const int tid = threadIdx.x;
    const int w = tid >> 5;
    const int wr = (w >> 2) & 1;     // rows wr*16
    const int wc = (w >> 1) & 1;     // cols wc*32 (2 n16 tiles)
    const int kh = w & 1;            // K half (128)
    const int bm = blockIdx.y * 32;
    const int bn = blockIdx.x * 64;

    // side job: rel table rows (z<2 only; 256 CTAs x 4 rows = all 1024)
    if (blockIdx.z < 2) {
        int cta = blockIdx.z * 128 + blockIdx.y * 4 + blockIdx.x;   // 0..255
        int r0 = cta * 4;
#pragma unroll
        for (int i = 0; i < 8; i++) {
            int idx = tid + i * 256;           // 0..2047 half2 slots (4 rows x 512)
            int lr = idx >> 9;                 // 0..3
            int cp = idx & 511;                // half2 col pair
            int row = r0 + lr;
            float pq = position[row];
            float pk0 = position[2 * cp];
            float pk1 = position[2 * cp + 1];
            float r0v = lg2f(fabsf(pq - pk0) + 1.f);
            float r1v = lg2f(fabsf(pq - pk1) + 1.f);
            *(uint32_t*)&g_rel[row * Lq + 2 * cp] = h2pack(r0v, r1v);
        }
    }

    // stage A 32x256 (2048 f4 slots, 8/thread) and B 64x256 (4096, 16/thread)
#pragma unroll
    for (int i = 0; i < 8; i++) {
        int s = tid + i * 256;
        int r = s >> 6;
        int c4 = (s & 63) << 2;
        float4 a = *(const float4*)&A[(bm + r) * Ee + c4];
        *(uint2*)&As[r][c4] = make_uint2(h2pack(a.x, a.y), h2pack(a.z, a.w));
    }
#pragma unroll
    for (int i = 0; i < 16; i++) {
        int s = tid + i * 256;
        int r = s >> 6;
        int c4 = (s & 63) << 2;
        float4 b = *(const float4*)&B[(bn + r) * Ee + c4];
        *(uint2*)&Bs[r][c4] = make_uint2(h2pack(b.x * scale, b.y * scale),
                                         h2pack(b.z * scale, b.w * scale));
    }
    __syncthreads();

    FragC c0, c1;
    wmma::fill_fragment(c0, 0.0f);
    wmma::fill_fragment(c1, 0.0f);
#pragma unroll
    for (int j = 0; j < 8; j++) {
        int kk = kh * 128 + j * 16;
        FragA a;
        FragBc b0, b1;
        wmma::load_matrix_sync(a, &As[wr * 16][kk], 264);
        wmma::load_matrix_sync(b0, &Bs[wc * 32][kk], 264);
        wmma::load_matrix_sync(b1, &Bs[wc * 32 + 16][kk], 264);
        wmma::mma_sync(c0, a, b0, c0);
        wmma::mma_sync(c1, a, b1, c1);
    }

    __syncthreads();   // all warps done reading Bs before overlay
    float (*Cs)[32][68] = reinterpret_cast<float(*)[32][68]>(&Bs[0][0]);
    wmma::store_matrix_sync(&Cs[kh][wr * 16][wc * 32], c0, 68, wmma::mem_row_major);
    wmma::store_matrix_sync(&Cs[kh][wr * 16][wc * 32 + 16], c1, 68, wmma::mem_row_major);
    __syncthreads();
#pragma unroll
    for (int i = 0; i < 2; i++) {
        int s = tid + i * 256;          // 512 f4 slots (32x64 fp32)
        int r = s >> 4;
        int c4 = (s & 15) << 2;
        float4 a = *(float4*)&Cs[0][r][c4];
        float4 b = *(float4*)&Cs[1][r][c4];
        *(uint2*)&C[(bm + r) * Ee + bn + c4] =
            make_uint2(h2pack(a.x + b.x, a.y + b.y), h2pack(a.z + b.z, a.w + b.w));
    }
}

// ---------------------------------------------------------------------------
// Output projection: out = O @ Wo^T + bo (fp16 in, fp32 out). UNCHANGED.
// Tile 32(M) x 32(N), 256 threads = 8 warps (2x2x2 splitK). grid (8,32)=256.
// ---------------------------------------------------------------------------
__global__ __launch_bounds__(256)
void gemm_out_kernel(const float* __restrict__ bias, float* __restrict__ C) {
    __shared__ __align__(16) __half As[32][264];
    __shared__ __align__(16) __half Bs[32][264];

    const int tid = threadIdx.x;
    const int w = tid >> 5;
    const int wr = (w >> 2) & 1;
    const int wc = (w >> 1) & 1;
    const int kh = w & 1;
    const int bm = blockIdx.y * 32;
    const int bn = blockIdx.x * 32;

#pragma unroll
    for (int i = 0; i < 4; i++) {
        int s = tid + i * 256;
        int r = s >> 5;
        int c8 = (s & 31) << 3;
        cp16(&As[r][c8], &g_ho[(bm + r) * Ee + c8]);
        cp16(&Bs[r][c8], &g_hwo[(bn + r) * Ee + c8]);
    }
    CP_COMMIT();
    CP_WAIT0();
    __syncthreads();

    FragC c0;
    wmma::fill_fragment(c0, 0.0f);
#pragma unroll
    for (int j = 0; j < 8; j++) {
        int kk = kh * 128 + j * 16;
        FragA a;
        FragBc b;
        wmma::load_matrix_sync(a, &As[wr * 16][kk], 264);
        wmma::load_matrix_sync(b, &Bs[wc * 16][kk], 264);
        wmma::mma_sync(c0, a, b, c0);
    }

    __syncthreads();   // done reading As before overlay
    float (*Cs)[32][36] = reinterpret_cast<float(*)[32][36]>(&As[0][0]);
    wmma::store_matrix_sync(&Cs[kh][wr * 16][wc * 16], c0, 36, wmma::mem_row_major);
    __syncthreads();
    {
        int r = tid >> 3, c4 = (tid & 7) << 2;
        float4 a = *(float4*)&Cs[0][r][c4];
        float4 b = *(float4*)&Cs[1][r][c4];
        const float4 bb = *(const float4*)&bias[bn + c4];
        float4 v = make_float4(a.x + b.x + bb.x, a.y + b.y + bb.y,
                               a.z + b.z + bb.z, a.w + b.w + bb.w);
        *(float4*)&C[(bm + r) * Ee + bn + c4] = v;
    }
}

// ---------------------------------------------------------------------------
// Flash attention, register-resident, PRECOMPUTED rel bias.
// Block = (head, 32 queries): grid (8, 32) = 256 blocks, 256 threads.
// Key tile 128 -> 8 iterations; warp tj handles key slices {tj*16, 64+tj*16}.
// softmax: p = ex2(fma(cf, rel, s)) — NO lg2/fabs in the hot loop.
// dyn smem: kvs[2][3][128][40] (61440) + rel_s[3][32][136] (26112) = 87552 B.
// ---------------------------------------------------------------------------
__global__ __launch_bounds__(256)
void flash_kernel(const float* __restrict__ Wr, const float* __restrict__ Wo) {
    const int h = blockIdx.x, hb = h * Dd, q0 = blockIdx.y * 32;
    const int tid = threadIdx.x, w = tid >> 5, lane = tid & 31;
    const int g = lane >> 2, tig = lane & 3;
    const int ti = w >> 2, tj = w & 3;

    __half (*kvs)[3][128][40] = reinterpret_cast<__half(*)[3][128][40]>(dyn_smem);
    __half (*rel_s)[32][136] = reinterpret_cast<__half(*)[32][136]>(dyn_smem + 61440);
    __shared__ __align__(16) __half qs[32][40];
    __shared__ float coeff_s[32];
    __shared__ float lred[2][4][16];

    auto stage = [&](int t, int buf) {
#pragma unroll
        for (int i = 0; i < 2; i++) {
            int s = tid + i * 256;
            int r = s >> 2, c8 = (s & 3) << 3;
            cp16(&kvs[0][buf][r][c8], &g_k[(t * 128 + r) * Ee + hb + c8]);
            cp16(&kvs[1][buf][r][c8], &g_v[(t * 128 + r) * Ee + hb + c8]);
        }
#pragma unroll
        for (int i = 0; i < 2; i++) {          // rel tile 32 x 128 halves
            int s = tid + i * 256;             // 512 cp16 slots
            int r = s >> 4, c8 = (s & 15) << 3;
            cp16(&rel_s[buf][r][c8], &g_rel[(q0 + r) * Lq + t * 128 + c8]);
        }
    };
    stage(0, 0); CP_COMMIT();
    stage(1, 1); CP_COMMIT();

    // side job: convert this block's share of Wo (overlaps staging latency)
    {
        int b = blockIdx.y * Hh + blockIdx.x;     // 0..255
        if (tid < 64) {
            int s = b * 64 + tid;
            float4 v = ((const float4*)Wo)[s];
            *(uint2*)&g_hwo[s * 4] = make_uint2(h2pack(v.x, v.y), h2pack(v.z, v.w));
        }
    }

    // q tile (pre-scaled): 32 rows x 32 halves = 128 x 16B
    if (tid < 128) {
        int r = tid >> 2, c8 = (tid & 3) << 3;
        *(uint4*)&qs[r][c8] = *(const uint4*)&g_q[(q0 + r) * Ee + hb + c8];
    }
    __syncthreads();
    if (tid < 32) {
        float c = 0.f;
#pragma unroll
        for (int d = 0; d < Dd; d++) c += __half2float(qs[tid][d]) * Wr[hb + d];
        coeff_s[tid] = c * (1.0f / LOG2E);   // q carries LOG2E/16; rel is lg2-based
    }
    __syncthreads();

    const float cf1 = coeff_s[ti * 16 + g];
    const float cf2 = coeff_s[ti * 16 + g + 8];
    const int srow = ti * 16 + g;              // block-local q row

    // Q A-fragments (m16k16 x2 over dims), fixed for all iterations
    uint32_t aq[2][4];
    {
        int row = ti * 16 + ((lane >> 3) & 1) * 8 + (lane & 7);
        int cs = ((lane >> 4) & 1) * 8;
        ldx4(aq[0], &qs[row][cs]);
        ldx4(aq[1], &qs[row][16 + cs]);
    }

    float oacc[4][4] = {};
    float lr1 = 0.f, lr2 = 0.f;

    for (int t = 0; t < 8; t++) {
        const int p = t % 3;
        CP_WAIT1();
        __syncthreads();

#pragma unroll
        for (int kt = 0; kt < 2; kt++) {
            const int kb = tj * 16 + kt * 64;   // this warp's key slice base

            // ---- GEMM1: S(16x16) in registers ----
            float sc0[4] = {}, sc1[4] = {};
            {
                uint32_t kb0[4], kb1[4];
                int krow = kb + ((lane >> 4) & 1) * 8 + (lane & 7);
                int kc = ((lane >> 3) & 1) * 8;
                ldx4(kb0, &kvs[0][p][krow][kc]);
                ldx4(kb1, &kvs[0][p][krow][16 + kc]);
                mma16816(sc0, aq[0], kb0[0], kb0[1]);
                mma16816(sc0, aq[1], kb1[0], kb1[1]);
                mma16816(sc1, aq[0], kb0[2], kb0[3]);
                mma16816(sc1, aq[1], kb1[2], kb1[3]);
            }

            // ---- softmax: p = ex2(s + cf*rel)  (rel precomputed) ----
            uint32_t pa[4];
            {
                int cb = kb + 2 * tig;
                float2 ra = __half22float2(*(const __half2*)&rel_s[p][srow][cb]);
                float2 rb = __half22float2(*(const __half2*)&rel_s[p][srow][cb + 8]);
                float2 rc = __half22float2(*(const __half2*)&rel_s[p][srow + 8][cb]);
                float2 rd = __half22float2(*(const __half2*)&rel_s[p][srow + 8][cb + 8]);
                float p00 = ex2f(fmaf(cf1, ra.x, sc0[0]));
                float p01 = ex2f(fmaf(cf1, ra.y, sc0[1]));
                float p02 = ex2f(fmaf(cf2, rc.x, sc0[2]));
                float p03 = ex2f(fmaf(cf2, rc.y, sc0[3]));
                float p10 = ex2f(fmaf(cf1, rb.x, sc1[0]));
                float p11 = ex2f(fmaf(cf1, rb.y, sc1[1]));
                float p12 = ex2f(fmaf(cf2, rd.x, sc1[2]));
                float p13 = ex2f(fmaf(cf2, rd.y, sc1[3]));
                lr1 += (p00 + p01) + (p10 + p11);
                lr2 += (p02 + p03) + (p12 + p13);
                pa[0] = h2pack(p00, p01);
                pa[1] = h2pack(p02, p03);
                pa[2] = h2pack(p10, p11);
                pa[3] = h2pack(p12, p13);
            }

            // ---- GEMM2: O(16x32) partial, warp-local key slice ----
            {
                uint32_t vb0[4], vb1[4];
                int vrow = kb + ((lane >> 3) & 1) * 8 + (lane & 7);
                int vc = ((lane >> 4) & 1) * 8;
                ldx4t(vb0, &kvs[1][p][vrow][vc]);
                ldx4t(vb1, &kvs[1][p][vrow][16 + vc]);
                mma16816(oacc[0], pa, vb0[0], vb0[1]);
                mma16816(oacc[1], pa, vb0[2], vb0[3]);
                mma16816(oacc[2], pa, vb1[0], vb1[1]);
                mma16816(oacc[3], pa, vb1[2], vb1[3]);
            }
        }

        if (t + 2 < 8) stage(t + 2, (t + 2) % 3);
        CP_COMMIT();
    }

    // ---- epilogue: reduce l and O partials across the 4 tj warps ----
    lr1 += __shfl_xor_sync(0xffffffffu, lr1, 1);
    lr1 += __shfl_xor_sync(0xffffffffu, lr1, 2);
    lr2 += __shfl_xor_sync(0xffffffffu, lr2, 1);
    lr2 += __shfl_xor_sync(0xffffffffu, lr2, 2);
    if (tig == 0) {
        lred[ti][tj][g] = lr1;
        lred[ti][tj][g + 8] = lr2;
    }
    __syncthreads();   // loop done: kvs free for overlay; lred complete

    float (*osc)[4][16][36] = reinterpret_cast<float(*)[4][16][36]>(dyn_smem);
#pragma unroll
    for (int nd = 0; nd < 4; nd++) {
        osc[ti][tj][g][nd * 8 + 2 * tig]         = oacc[nd][0];
        osc[ti][tj][g][nd * 8 + 2 * tig + 1]     = oacc[nd][1];
        osc[ti][tj][g + 8][nd * 8 + 2 * tig]     = oacc[nd][2];
        osc[ti][tj][g + 8][nd * 8 + 2 * tig + 1] = oacc[nd][3];
    }
    __syncthreads();

    {
        int r = tid >> 3;
        int c = (tid & 7) << 2;
        int rt = r >> 4, rr = r & 15;
        float l = (lred[rt][0][rr] + lred[rt][1][rr]) +
                  (lred[rt][2][rr] + lred[rt][3][rr]);
        float inv = 1.f / l;
        float4 a0 = *(float4*)&osc[rt][0][rr][c];
        float4 a1 = *(float4*)&osc[rt][1][rr][c];
        float4 a2 = *(float4*)&osc[rt][2][rr][c];
        float4 a3 = *(float4*)&osc[rt][3][rr][c];
        float x = (a0.x + a1.x + a2.x + a3.x) * inv;
        float y = (a0.y + a1.y + a2.y + a3.y) * inv;
        float z = (a0.z + a1.z + a2.z + a3.z) * inv;
        float u = (a0.w + a1.w + a2.w + a3.w) * inv;
        *(uint2*)&g_ho[(q0 + r) * Ee + hb + c] = make_uint2(h2pack(x, y), h2pack(z, u));
    }
}

// ---------------------------------------------------------------------------
// launcher — 3 kernels total
// ---------------------------------------------------------------------------
extern "C" void kernel_launch(void* const* d_in, const int* in_sizes, int n_in,
                              void* d_out, int out_size) {
    const float* V  = (const float*)d_in[0];
    const float* K_ = (const float*)d_in[1];
    const float* Q  = (const float*)d_in[2];
    const float* position = (const float*)d_in[3];
    const float* Wq = (const float*)d_in[4];
    const float* Wk = (const float*)d_in[5];
    const float* Wv = (const float*)d_in[6];
    const float* Wr = (const float*)d_in[7];
    const float* Wo = (const float*)d_in[8];
    const float* bo = (const float*)d_in[9];
    float* out = (float*)d_out;

    const int qkv_smem = 50688;       // As 16896 + Bs 33792
    const int flash_smem = 87552;     // kvs 61440 + rel 26112
    static bool attr_set = false;
    if (!attr_set) {
        cudaFuncSetAttribute(gemm_qkv_kernel,
                             cudaFuncAttributeMaxDynamicSharedMemorySize, qkv_smem);
        cudaFuncSetAttribute(flash_kernel,
                             cudaFuncAttributeMaxDynamicSharedMemorySize, flash_smem);
        attr_set = true;
    }

    gemm_qkv_kernel<<<dim3(Ee / 64, Lq / 32, 3), 256, qkv_smem>>>(Q, K_, V, Wq, Wk, Wv, position);
    flash_kernel<<<dim3(Hh, Lq / 32), 256, flash_smem>>>(Wr, Wo);
    gemm_out_kernel<<<dim3(Ee / 32, Lq / 32), 256>>>(bo, out);
}

// round 17
// speedup vs baseline: 1.0313x; 1.0313x over previous
#include <cuda_runtime.h>
#include <cuda_fp16.h>
#include <math.h>
#include <stdint.h>

#define Lq 1024
#define Ee 256
#define Hh 8
#define Dd 32
#define LOG2E 1.4426950408889634f
#define QSCALE (0.0625f * LOG2E)

// scratch (allocation-free rule: __device__ globals)
__device__ __half g_q[Lq * Ee];     // projected q (pre-scaled by LOG2E/16)
__device__ __half g_k[Lq * Ee];
__device__ __half g_v[Lq * Ee];
__device__ __half g_ho[Lq * Ee];    // attention output (fp16)
__device__ __half g_hwo[Ee * Ee];   // fp16 Wo (converted inside flash)

extern __shared__ char dyn_smem[];

__device__ __forceinline__ float ex2f(float x) {
    float y; asm("ex2.approx.f32 %0, %1;" : "=f"(y) : "f"(x)); return y;
}
__device__ __forceinline__ float lg2f(float x) {
    float y; asm("lg2.approx.f32 %0, %1;" : "=f"(y) : "f"(x)); return y;
}
__device__ __forceinline__ void cp16(void* smem, const void* gmem) {
    uint32_t s = (uint32_t)__cvta_generic_to_shared(smem);
    asm volatile("cp.async.cg.shared.global [%0], [%1], 16;\n" :: "r"(s), "l"(gmem));
}
#define CP_COMMIT() asm volatile("cp.async.commit_group;\n" ::: "memory")
#define CP_WAIT1()  asm volatile("cp.async.wait_group 1;\n" ::: "memory")
#define CP_WAIT0()  asm volatile("cp.async.wait_group 0;\n" ::: "memory")

__device__ __forceinline__ uint32_t h2pack(float x, float y) {
    __half2 h = __floats2half2_rn(x, y);
    return *(uint32_t*)&h;
}
__device__ __forceinline__ void ldx4(uint32_t r[4], const void* p) {
    uint32_t a = (uint32_t)__cvta_generic_to_shared(p);
    asm volatile("ldmatrix.sync.aligned.m8n8.x4.shared.b16 {%0,%1,%2,%3}, [%4];"
                 : "=r"(r[0]), "=r"(r[1]), "=r"(r[2]), "=r"(r[3]) : "r"(a));
}
__device__ __forceinline__ void ldx4t(uint32_t r[4], const void* p) {
    uint32_t a = (uint32_t)__cvta_generic_to_shared(p);
    asm volatile("ldmatrix.sync.aligned.m8n8.x4.trans.shared.b16 {%0,%1,%2,%3}, [%4];"
                 : "=r"(r[0]), "=r"(r[1]), "=r"(r[2]), "=r"(r[3]) : "r"(a));
}
__device__ __forceinline__ void mma16816(float c[4], const uint32_t a[4],
                                         uint32_t b0, uint32_t b1) {
    asm volatile("mma.sync.aligned.m16n8k16.row.col.f32.f16.f16.f32 "
                 "{%0,%1,%2,%3}, {%4,%5,%6,%7}, {%8,%9}, {%0,%1,%2,%3};"
                 : "+f"(c[0]), "+f"(c[1]), "+f"(c[2]), "+f"(c[3])
                 : "r"(a[0]), "r"(a[1]), "r"(a[2]), "r"(a[3]), "r"(b0), "r"(b1));
}

// ---------------------------------------------------------------------------
// QKV projection, SINGLE-SHOT K=256, explicit mma, NO splitK, NO epilogue.
// Tile 32(M) x 64(N): grid (4, 32, 3) = 384 CTAs, 256 threads (8 warps 2x4,
// each warp one 16x16 output tile, full-K chains of 16 mma per accumulator).
// Accumulators stored DIRECTLY to gmem as half2 (documented 16816 C layout).
// Wq scaled by LOG2E/16 (folds 1/sqrt(E) + exp2 base change).
// dyn smem: As 16896 + Bs 33792 = 50688 B.
// ---------------------------------------------------------------------------
__global__ __launch_bounds__(256)
void gemm_qkv_kernel(const float* __restrict__ Q, const float* __restrict__ K_,
                     const float* __restrict__ V,
                     const float* __restrict__ Wq, const float* __restrict__ Wk,
                     const float* __restrict__ Wv) {
    const float* A = blockIdx.z == 0 ? Q  : (blockIdx.z == 1 ? K_ : V);
    const float* B = blockIdx.z == 0 ? Wq : (blockIdx.z == 1 ? Wk : Wv);
    __half*      C = blockIdx.z == 0 ? g_q : (blockIdx.z == 1 ? g_k : g_v);
    const float scale = blockIdx.z == 0 ? QSCALE : 1.0f;

    __half (*As)[264] = reinterpret_cast<__half(*)[264]>(dyn_smem);
    __half (*Bs)[264] = reinterpret_cast<__half(*)[264]>(dyn_smem + 16896);

    const int tid = threadIdx.x;
    const int w = tid >> 5, lane = tid & 31;
    const int wr = w >> 2;           // 0..1 : rows wr*16
    const int wc = w & 3;            // 0..3 : cols wc*16
    const int bm = blockIdx.y * 32;
    const int bn = blockIdx.x * 64;

    // stage A 32x256 (2048 f4 slots, 8/thread) and B 64x256 (4096, 16/thread)
#pragma unroll
    for (int i = 0; i < 8; i++) {
        int s = tid + i * 256;
        int r = s >> 6;
        int c4 = (s & 63) << 2;
        float4 a = *(const float4*)&A[(bm + r) * Ee + c4];
        *(uint2*)&As[r][c4] = make_uint2(h2pack(a.x, a.y), h2pack(a.z, a.w));
    }
#pragma unroll
    for (int i = 0; i < 16; i++) {
        int s = tid + i * 256;
        int r = s >> 6;
        int c4 = (s & 63) << 2;
        float4 b = *(const float4*)&B[(bn + r) * Ee + c4];
        *(uint2*)&Bs[r][c4] = make_uint2(h2pack(b.x * scale, b.y * scale),
                                         h2pack(b.z * scale, b.w * scale));
    }
    __syncthreads();

    // full-K mma: 16 k-steps, 2 accumulators (n8 groups)
    float sc0[4] = {}, sc1[4] = {};
    const int arow = wr * 16 + ((lane >> 3) & 1) * 8 + (lane & 7);
    const int acol = ((lane >> 4) & 1) * 8;
    const int brow = wc * 16 + ((lane >> 4) & 1) * 8 + (lane & 7);
    const int bcol = ((lane >> 3) & 1) * 8;
#pragma unroll
    for (int k = 0; k < 16; k++) {
        uint32_t a[4], b[4];
        ldx4(a, &As[arow][k * 16 + acol]);
        ldx4(b, &Bs[brow][k * 16 + bcol]);
        mma16816(sc0, a, b[0], b[1]);
        mma16816(sc1, a, b[2], b[3]);
    }

    // direct store (16816 C layout: c0/c1 -> row g cols 2t/2t+1; c2/c3 -> row g+8)
    {
        const int g = lane >> 2, tg = lane & 3;
        int row0 = bm + wr * 16 + g;
        int col = bn + wc * 16 + 2 * tg;
        *(uint32_t*)&C[row0 * Ee + col]           = h2pack(sc0[0], sc0[1]);
        *(uint32_t*)&C[(row0 + 8) * Ee + col]     = h2pack(sc0[2], sc0[3]);
        *(uint32_t*)&C[row0 * Ee + col + 8]       = h2pack(sc1[0], sc1[1]);
        *(uint32_t*)&C[(row0 + 8) * Ee + col + 8] = h2pack(sc1[2], sc1[3]);
    }
}

// ---------------------------------------------------------------------------
// Output projection: out = O @ Wo^T + bo (fp16 in, fp32 out).
// Tile 32(M) x 32(N), 128 threads (4 warps 2x2, each 16x16, full-K chains).
// grid (8, 32) = 256 CTAs. Bias added in registers; DIRECT fp32 stores.
// ---------------------------------------------------------------------------
__global__ __launch_bounds__(128)
void gemm_out_kernel(const float* __restrict__ bias, float* __restrict__ C) {
    __shared__ __align__(16) __half As[32][264];
    __shared__ __align__(16) __half Bs[32][264];

    const int tid = threadIdx.x;
    const int w = tid >> 5, lane = tid & 31;
    const int wr = w >> 1;           // rows wr*16
    const int wc = w & 1;            // cols wc*16
    const int bm = blockIdx.y * 32;
    const int bn = blockIdx.x * 32;

    // stage: A and B 32x256 fp16, 1024 cp16 slots each -> 8 per thread each
#pragma unroll
    for (int i = 0; i < 8; i++) {
        int s = tid + i * 128;
        int r = s >> 5;
        int c8 = (s & 31) << 3;
        cp16(&As[r][c8], &g_ho[(bm + r) * Ee + c8]);
        cp16(&Bs[r][c8], &g_hwo[(bn + r) * Ee + c8]);
    }
    CP_COMMIT();
    CP_WAIT0();
    __syncthreads();

    float sc0[4] = {}, sc1[4] = {};
    const int arow = wr * 16 + ((lane >> 3) & 1) * 8 + (lane & 7);
    const int acol = ((lane >> 4) & 1) * 8;
    const int brow = wc * 16 + ((lane >> 4) & 1) * 8 + (lane & 7);
    const int bcol = ((lane >> 3) & 1) * 8;
#pragma unroll
    for (int k = 0; k < 16; k++) {
        uint32_t a[4], b[4];
        ldx4(a, &As[arow][k * 16 + acol]);
        ldx4(b, &Bs[brow][k * 16 + bcol]);
        mma16816(sc0, a, b[0], b[1]);
        mma16816(sc1, a, b[2], b[3]);
    }

    // direct fp32 store with register bias
    {
        const int g = lane >> 2, tg = lane & 3;
        int row0 = bm + wr * 16 + g;
        int col = bn + wc * 16 + 2 * tg;
        float b0 = bias[col],     b1 = bias[col + 1];
        float b8 = bias[col + 8], b9 = bias[col + 9];
        *(float2*)&C[row0 * Ee + col]           = make_float2(sc0[0] + b0, sc0[1] + b1);
        *(float2*)&C[(row0 + 8) * Ee + col]     = make_float2(sc0[2] + b0, sc0[3] + b1);
        *(float2*)&C[row0 * Ee + col + 8]       = make_float2(sc1[0] + b8, sc1[1] + b9);
        *(float2*)&C[(row0 + 8) * Ee + col + 8] = make_float2(sc1[2] + b8, sc1[3] + b9);
    }
}

// ---------------------------------------------------------------------------
// Flash attention, register-resident (explicit mma + ldmatrix). R14 version.
// Block = (head, 32 queries): grid (8, 32) = 256 blocks, 256 threads.
// Key tile 128 -> 8 iterations; ONE __syncthreads per iteration.
// dyn smem: kvs[2][3][128][40] fp16 = 61440 B.
// ---------------------------------------------------------------------------
__global__ __launch_bounds__(256)
void flash_kernel(const float* __restrict__ position, const float* __restrict__ Wr,
                  const float* __restrict__ Wo) {
    const int h = blockIdx.x, hb = h * Dd, q0 = blockIdx.y * 32;
    const int tid = threadIdx.x, w = tid >> 5, lane = tid & 31;
    const int g = lane >> 2, tig = lane & 3;
    const int ti = w >> 2, tj = w & 3;

    __half (*kvs)[3][128][40] = reinterpret_cast<__half(*)[3][128][40]>(dyn_smem);
    __shared__ __align__(16) __half qs[32][40];
    __shared__ float posk_s[3][128];
    __shared__ float posq_s[32], coeff_s[32];
    __shared__ float lred[2][4][16];

    auto stage = [&](int t, int buf) {
#pragma unroll
        for (int i = 0; i < 2; i++) {
            int s = tid + i * 256;
            int r = s >> 2, c8 = (s & 3) << 3;
            cp16(&kvs[0][buf][r][c8], &g_k[(t * 128 + r) * Ee + hb + c8]);
            cp16(&kvs[1][buf][r][c8], &g_v[(t * 128 + r) * Ee + hb + c8]);
        }
        if (tid < 32) cp16(&posk_s[buf][tid * 4], &position[t * 128 + tid * 4]);
    };
    stage(0, 0); CP_COMMIT();
    stage(1, 1); CP_COMMIT();

    // side job: convert this block's share of Wo (overlaps staging latency)
    {
        int b = blockIdx.y * Hh + blockIdx.x;     // 0..255
        if (tid < 64) {
            int s = b * 64 + tid;
            float4 v = ((const float4*)Wo)[s];
            *(uint2*)&g_hwo[s * 4] = make_uint2(h2pack(v.x, v.y), h2pack(v.z, v.w));
        }
    }

    // q tile (pre-scaled): 32 rows x 32 halves = 128 x 16B
    if (tid < 128) {
        int r = tid >> 2, c8 = (tid & 3) << 3;
        *(uint4*)&qs[r][c8] = *(const uint4*)&g_q[(q0 + r) * Ee + hb + c8];
    }
    if (tid < 32) posq_s[tid] = position[q0 + tid];
    __syncthreads();
    if (tid < 32) {
        float c = 0.f;
#pragma unroll
        for (int d = 0; d < Dd; d++) c += __half2float(qs[tid][d]) * Wr[hb + d];
        coeff_s[tid] = c * (1.0f / LOG2E);   // q carries LOG2E/16; lg2 term needs c/LOG2E
    }
    __syncthreads();

    const float pq1 = posq_s[ti * 16 + g];
    const float pq2 = posq_s[ti * 16 + g + 8];
    const float cf1 = coeff_s[ti * 16 + g];
    const float cf2 = coeff_s[ti * 16 + g + 8];

    // Q A-fragments (m16k16 x2 over dims), fixed for all iterations
    uint32_t aq[2][4];
    {
        int row = ti * 16 + ((lane >> 3) & 1) * 8 + (lane & 7);
        int cs = ((lane >> 4) & 1) * 8;
        ldx4(aq[0], &qs[row][cs]);
        ldx4(aq[1], &qs[row][16 + cs]);
    }

    float oacc[4][4] = {};
    float lr1 = 0.f, lr2 = 0.f;

    for (int t = 0; t < 8; t++) {
        const int p = t % 3;
        CP_WAIT1();
        __syncthreads();

#pragma unroll
        for (int kt = 0; kt < 2; kt++) {
            const int kb = tj * 16 + kt * 64;   // this warp's key slice base

            // ---- GEMM1: S(16x16) in registers ----
            float sc0[4] = {}, sc1[4] = {};
            {
                uint32_t kb0[4], kb1[4];
                int krow = kb + ((lane >> 4) & 1) * 8 + (lane & 7);
                int kc = ((lane >> 3) & 1) * 8;
                ldx4(kb0, &kvs[0][p][krow][kc]);
                ldx4(kb1, &kvs[0][p][krow][16 + kc]);
                mma16816(sc0, aq[0], kb0[0], kb0[1]);
                mma16816(sc0, aq[1], kb1[0], kb1[1]);
                mma16816(sc1, aq[0], kb0[2], kb0[3]);
                mma16816(sc1, aq[1], kb1[2], kb1[3]);
            }

            // ---- softmax in registers ----
            uint32_t pa[4];
            {
                int cb = kb + 2 * tig;
                float pk0 = posk_s[p][cb],     pk1 = posk_s[p][cb + 1];
                float pk8 = posk_s[p][cb + 8], pk9 = posk_s[p][cb + 9];
                float p00 = ex2f(sc0[0] + cf1 * lg2f(fabsf(pq1 - pk0) + 1.f));
                float p01 = ex2f(sc0[1] + cf1 * lg2f(fabsf(pq1 - pk1) + 1.f));
                float p02 = ex2f(sc0[2] + cf2 * lg2f(fabsf(pq2 - pk0) + 1.f));
                float p03 = ex2f(sc0[3] + cf2 * lg2f(fabsf(pq2 - pk1) + 1.f));
                float p10 = ex2f(sc1[0] + cf1 * lg2f(fabsf(pq1 - pk8) + 1.f));
                float p11 = ex2f(sc1[1] + cf1 * lg2f(fabsf(pq1 - pk9) + 1.f));
                float p12 = ex2f(sc1[2] + cf2 * lg2f(fabsf(pq2 - pk8) + 1.f));
                float p13 = ex2f(sc1[3] + cf2 * lg2f(fabsf(pq2 - pk9) + 1.f));
                lr1 += (p00 + p01) + (p10 + p11);
                lr2 += (p02 + p03) + (p12 + p13);
                pa[0] = h2pack(p00, p01);
                pa[1] = h2pack(p02, p03);
                pa[2] = h2pack(p10, p11);
                pa[3] = h2pack(p12, p13);
            }

            // ---- GEMM2: O(16x32) partial, warp-local key slice ----
            {
                uint32_t vb0[4], vb1[4];
                int vrow = kb + ((lane >> 3) & 1) * 8 + (lane & 7);
                int vc = ((lane >> 4) & 1) * 8;
                ldx4t(vb0, &kvs[1][p][vrow][vc]);
                ldx4t(vb1, &kvs[1][p][vrow][16 + vc]);
                mma16816(oacc[0], pa, vb0[0], vb0[1]);
                mma16816(oacc[1], pa, vb0[2], vb0[3]);
                mma16816(oacc[2], pa, vb1[0], vb1[1]);
                mma16816(oacc[3], pa, vb1[2], vb1[3]);
            }
        }

        if (t + 2 < 8) stage(t + 2, (t + 2) % 3);
        CP_COMMIT();
    }

    // ---- epilogue: reduce l and O partials across the 4 tj warps ----
    lr1 += __shfl_xor_sync(0xffffffffu, lr1, 1);
    lr1 += __shfl_xor_sync(0xffffffffu, lr1, 2);
    lr2 += __shfl_xor_sync(0xffffffffu, lr2, 1);
    lr2 += __shfl_xor_sync(0xffffffffu, lr2, 2);
    if (tig == 0) {
        lred[ti][tj][g] = lr1;
        lred[ti][tj][g + 8] = lr2;
    }
    __syncthreads();   // loop done: kvs free for overlay; lred complete

    float (*osc)[4][16][36] = reinterpret_cast<float(*)[4][16][36]>(dyn_smem);
#pragma unroll
    for (int nd = 0; nd < 4; nd++) {
        osc[ti][tj][g][nd * 8 + 2 * tig]         = oacc[nd][0];
        osc[ti][tj][g][nd * 8 + 2 * tig + 1]     = oacc[nd][1];
        osc[ti][tj][g + 8][nd * 8 + 2 * tig]     = oacc[nd][2];
        osc[ti][tj][g + 8][nd * 8 + 2 * tig + 1] = oacc[nd][3];
    }
    __syncthreads();

    {
        int r = tid >> 3;
        int c = (tid & 7) << 2;
        int rt = r >> 4, rr = r & 15;
        float l = (lred[rt][0][rr] + lred[rt][1][rr]) +
                  (lred[rt][2][rr] + lred[rt][3][rr]);
        float inv = 1.f / l;
        float4 a0 = *(float4*)&osc[rt][0][rr][c];
        float4 a1 = *(float4*)&osc[rt][1][rr][c];
        float4 a2 = *(float4*)&osc[rt][2][rr][c];
        float4 a3 = *(float4*)&osc[rt][3][rr][c];
        float x = (a0.x + a1.x + a2.x + a3.x) * inv;
        float y = (a0.y + a1.y + a2.y + a3.y) * inv;
        float z = (a0.z + a1.z + a2.z + a3.z) * inv;
        float u = (a0.w + a1.w + a2.w + a3.w) * inv;
        *(uint2*)&g_ho[(q0 + r) * Ee + hb + c] = make_uint2(h2pack(x, y), h2pack(z, u));
    }
}

// ---------------------------------------------------------------------------
// launcher — 3 kernels total
// ---------------------------------------------------------------------------
extern "C" void kernel_launch(void* const* d_in, const int* in_sizes, int n_in,
                              void* d_out, int out_size) {
    const float* V  = (const float*)d_in[0];
    const float* K_ = (const float*)d_in[1];
    const float* Q  = (const float*)d_in[2];
    const float* position = (const float*)d_in[3];
    const float* Wq = (const float*)d_in[4];
    const float* Wk = (const float*)d_in[5];
    const float* Wv = (const float*)d_in[6];
    const float* Wr = (const float*)d_in[7];
    const float* Wo = (const float*)d_in[8];
    const float* bo = (const float*)d_in[9];
    float* out = (float*)d_out;

    const int qkv_smem = 50688;       // As 16896 + Bs 33792
    const int flash_smem = 61440;     // kvs
    static bool attr_set = false;
    if (!attr_set) {
        cudaFuncSetAttribute(gemm_qkv_kernel,
                             cudaFuncAttributeMaxDynamicSharedMemorySize, qkv_smem);
        cudaFuncSetAttribute(flash_kernel,
                             cudaFuncAttributeMaxDynamicSharedMemorySize, flash_smem);
        attr_set = true;
    }

    gemm_qkv_kernel<<<dim3(Ee / 64, Lq / 32, 3), 256, qkv_smem>>>(Q, K_, V, Wq, Wk, Wv);
    flash_kernel<<<dim3(Hh, Lq / 32), 256, flash_smem>>>(position, Wr, Wo);
    gemm_out_kernel<<<dim3(Ee / 32, Lq / 32), 128>>>(bo, out);
}